// round 8
// baseline (speedup 1.0000x reference)
#include <cuda_runtime.h>
#include <cuda_fp16.h>
#include <cstdint>
#include <cstddef>

#define B_DIM   4096
#define I_DIM   256
#define O_DIM   256
#define K_BASIS (I_DIM * 64)                /* 16384 */
#define K_TOT   (K_BASIS + 2 * I_DIM)       /* 16896 */
#define N_TOT   (2 * O_DIM)                 /* 512   */

#define BM 64
#define BN 128
#define BK 64                                /* 128 bytes per k-row */
#define STAGES 4
#define NITER (K_TOT / BK)                   /* 264 */

#define STAGE_BYTES ((BM + BN) * 128)        /* 24 KB */
#define SMEM_TOTAL  (STAGES * STAGE_BYTES)   /* 96 KB */

// ---------------- device scratch ----------------
__device__ __align__(128) __half g_A[(size_t)B_DIM * K_TOT];   // 138 MB fp16 A
__device__ __align__(128) __half g_Wt[(size_t)N_TOT * K_TOT];  // 17 MB packed W^T [n][k]
__device__ float g_bias[N_TOT];

// ---------------- PTX helpers ----------------
__device__ __forceinline__ uint32_t smem_u32(const void* p) {
    uint32_t a;
    asm("{ .reg .u64 t; cvta.to.shared.u64 t, %1; cvt.u32.u64 %0, t; }" : "=r"(a) : "l"(p));
    return a;
}
__device__ __forceinline__ void cp_async16(uint32_t saddr, const void* gptr) {
    asm volatile("cp.async.cg.shared.global [%0], [%1], 16;\n" :: "r"(saddr), "l"(gptr));
}
#define CP_COMMIT() asm volatile("cp.async.commit_group;\n" ::: "memory")
#define CP_WAIT(N)  asm volatile("cp.async.wait_group %0;\n" :: "n"(N) : "memory")

__device__ __forceinline__ void ldsm_x4(uint32_t* r, uint32_t saddr) {
    asm volatile("ldmatrix.sync.aligned.m8n8.x4.shared.b16 {%0,%1,%2,%3}, [%4];"
                 : "=r"(r[0]), "=r"(r[1]), "=r"(r[2]), "=r"(r[3]) : "r"(saddr));
}
__device__ __forceinline__ void mma16816(float* d, const uint32_t* a, const uint32_t* b) {
    asm volatile(
        "mma.sync.aligned.m16n8k16.row.col.f32.f16.f16.f32 "
        "{%0,%1,%2,%3}, {%4,%5,%6,%7}, {%8,%9}, {%0,%1,%2,%3};\n"
        : "+f"(d[0]), "+f"(d[1]), "+f"(d[2]), "+f"(d[3])
        : "r"(a[0]), "r"(a[1]), "r"(a[2]), "r"(a[3]), "r"(b[0]), "r"(b[1]));
}

// ---------------- kernel 1: bias vector ----------------
__global__ void bias_kernel(const float* __restrict__ br, const float* __restrict__ bi) {
    int n = blockIdx.x * blockDim.x + threadIdx.x;
    if (n >= N_TOT) return;
    const float* src = (n < O_DIM) ? br : bi;
    int o = n & (O_DIM - 1);
    float s = 0.f;
    for (int i = 0; i < I_DIM; ++i) s += src[i * O_DIM + o];
    g_bias[n] = s;
}

// ---------------- kernel 2: pack W^T [n][k] fp16 ----------------
__global__ void pack_kernel(const float* __restrict__ rw, const float* __restrict__ cw,
                            const float* __restrict__ swr, const float* __restrict__ swi) {
    int gid = blockIdx.x * blockDim.x + threadIdx.x;
    int n = gid / K_TOT;
    int k = gid - n * K_TOT;
    int o = n & (O_DIM - 1);
    bool re = (n < O_DIM);
    float val;
    if (k < K_BASIS) {
        int i = k >> 6, uv = k & 63;
        const float* w = re ? rw : cw;
        val = w[((size_t)(i * O_DIM + o)) * 64 + uv];
    } else if (k < K_BASIS + I_DIM) {
        int i = k - K_BASIS;
        val = re ? swr[i * O_DIM + o] : swi[i * O_DIM + o];
    } else {
        int i = k - K_BASIS - I_DIM;
        val = re ? -swi[i * O_DIM + o] : swr[i * O_DIM + o];
    }
    g_Wt[(size_t)n * K_TOT + k] = __float2half(val);
}

// ---------------- kernel 3: materialize A (vectorized stores) ----------------
__global__ void basis_kernel(const float* __restrict__ x_re, const float* __restrict__ x_im) {
    int b = blockIdx.x;
    int i = threadIdx.x;
    float xr = x_re[b * I_DIM + i];
    float xi = x_im[b * I_DIM + i];
    float eu[8], ev[8];
#pragma unroll
    for (int u = 0; u < 8; ++u) {
        float lu = -2.0f + (float)u * (4.0f / 7.0f);
        float dr = xr - lu;  eu[u] = __expf(-dr * dr);
        float di = xi - lu;  ev[u] = __expf(-di * di);
    }
    uint4* dst = (uint4*)(g_A + (size_t)b * K_TOT + (size_t)i * 64);
#pragma unroll
    for (int u = 0; u < 8; ++u) {
        uint4 row;
        __half2* h = (__half2*)&row;
#pragma unroll
        for (int v = 0; v < 8; v += 2)
            h[v >> 1] = __floats2half2_rn(eu[u] * ev[v], eu[u] * ev[v + 1]);
        dst[u] = row;
    }
    float sr = xr / (1.f + __expf(-xr));
    float si = xi / (1.f + __expf(-xi));
    g_A[(size_t)b * K_TOT + K_BASIS + i]         = __float2half(sr);
    g_A[(size_t)b * K_TOT + K_BASIS + I_DIM + i] = __float2half(si);
}

// ---------------- kernel 4: GEMM (ldmatrix + mma.sync, 4-stage cp.async, 2 CTA/SM) ----
// stage layout: A tile [64 rows][128B], then B tile [128 rows][128B]
// swizzle: 16B chunk c of row r stored at (c ^ (r & 7))
__device__ __forceinline__ void copy_stage(uint32_t sA, uint32_t sB,
                                           const __half* gA, const __half* gB,
                                           int k0, int tid) {
#pragma unroll
    for (int r = 0; r < 2; ++r) {          // A: 512 chunks
        int cc  = tid + (r << 8);
        int row = cc >> 3, ch = cc & 7;
        uint32_t d = (uint32_t)(row << 7) + (uint32_t)((ch ^ (row & 7)) << 4);
        cp_async16(sA + d, gA + (size_t)row * K_TOT + k0 + (ch << 3));
    }
#pragma unroll
    for (int r = 0; r < 4; ++r) {          // B: 1024 chunks
        int cc  = tid + (r << 8);
        int row = cc >> 3, ch = cc & 7;
        uint32_t d = (uint32_t)(row << 7) + (uint32_t)((ch ^ (row & 7)) << 4);
        cp_async16(sB + d, gB + (size_t)row * K_TOT + k0 + (ch << 3));
    }
}

__global__ __launch_bounds__(256, 2)
void gemm_kernel(float* __restrict__ out) {
    extern __shared__ __align__(128) char smem[];
    uint32_t sbase = smem_u32(smem);

    int tid  = threadIdx.x;
    int warp = tid >> 5, lane = tid & 31;
    int bm = blockIdx.x * BM, bn = blockIdx.y * BN;
    int wm = (warp >> 2) * 32;   // warp M offset (0,32)
    int wn = (warp & 3) * 32;    // warp N offset (0..96)

    // ldmatrix per-lane addressing constants
    int ra  = wm + (((lane >> 3) & 1) << 3) + (lane & 7);  // A row (without mi*16)
    int ca  = lane >> 4;                                   // A k16-half chunk select
    int swa = ra & 7;
    int nb  = wn + ((lane >> 4) << 3) + (lane & 7);        // B row (without nn*16)
    int cb  = (lane >> 3) & 1;                             // B k16-half chunk select
    int swb = nb & 7;

    const __half* gA = g_A  + (size_t)bm * K_TOT;
    const __half* gB = g_Wt + (size_t)bn * K_TOT;

    float acc[2][4][4];
#pragma unroll
    for (int mi = 0; mi < 2; ++mi)
#pragma unroll
        for (int ni = 0; ni < 4; ++ni)
#pragma unroll
            for (int c = 0; c < 4; ++c) acc[mi][ni][c] = 0.f;

    // prologue
#pragma unroll
    for (int t = 0; t < STAGES - 1; ++t) {
        copy_stage(sbase + t * STAGE_BYTES, sbase + t * STAGE_BYTES + BM * 128,
                   gA, gB, t * BK, tid);
        CP_COMMIT();
    }

    int s = 0;
    for (int kt = 0; kt < NITER; ++kt) {
        CP_WAIT(STAGES - 2);
        __syncthreads();

        {   // issue next-stage copy first so it overlaps the MMA block
            int knext = kt + STAGES - 1;
            if (knext < NITER) {
                int j = s - 1;
                if (j < 0) j += STAGES;                  // knext % STAGES
                copy_stage(sbase + j * STAGE_BYTES, sbase + j * STAGE_BYTES + BM * 128,
                           gA, gB, knext * BK, tid);
            }
            CP_COMMIT();
        }

        uint32_t baseA = sbase + s * STAGE_BYTES + (uint32_t)(ra << 7);
        uint32_t baseB = sbase + s * STAGE_BYTES + BM * 128 + (uint32_t)(nb << 7);

#pragma unroll
        for (int ks = 0; ks < 4; ++ks) {               // four k16 steps per BK=64
            uint32_t af[2][4];
            uint32_t bf[4][2];
            uint32_t offA = (uint32_t)(((2 * ks + ca) ^ swa) << 4);
            uint32_t offB = (uint32_t)(((2 * ks + cb) ^ swb) << 4);
#pragma unroll
            for (int mi = 0; mi < 2; ++mi)
                ldsm_x4(af[mi], baseA + (uint32_t)(mi * 16 * 128) + offA);
#pragma unroll
            for (int nn = 0; nn < 2; ++nn) {
                uint32_t t4[4];
                ldsm_x4(t4, baseB + (uint32_t)(nn * 16 * 128) + offB);
                bf[2 * nn][0]     = t4[0];
                bf[2 * nn][1]     = t4[1];
                bf[2 * nn + 1][0] = t4[2];
                bf[2 * nn + 1][1] = t4[3];
            }
#pragma unroll
            for (int mi = 0; mi < 2; ++mi)
#pragma unroll
                for (int ni = 0; ni < 4; ++ni)
                    mma16816(acc[mi][ni], af[mi], bf[ni]);
        }
        if (++s == STAGES) s = 0;
    }

    // epilogue: out[(b*O + o)*2 + part] = acc + bias[n]
    int g = lane >> 2, t = lane & 3;
#pragma unroll
    for (int mi = 0; mi < 2; ++mi) {
#pragma unroll
        for (int ni = 0; ni < 4; ++ni) {
            int row0 = bm + wm + mi * 16 + g;
            int col0 = bn + wn + ni * 8 + 2 * t;
            float b0 = g_bias[col0];
            float b1 = g_bias[col0 + 1];
            int o0 = col0 & (O_DIM - 1);
            int part = col0 >> 8;          // whole 128-wide tile is same part
            size_t base0 = ((size_t)row0 * O_DIM + o0) * 2 + part;
            size_t base8 = ((size_t)(row0 + 8) * O_DIM + o0) * 2 + part;
            out[base0]     = acc[mi][ni][0] + b0;
            out[base0 + 2] = acc[mi][ni][1] + b1;
            out[base8]     = acc[mi][ni][2] + b0;
            out[base8 + 2] = acc[mi][ni][3] + b1;
        }
    }
}

// ---------------- launch ----------------
extern "C" void kernel_launch(void* const* d_in, const int* in_sizes, int n_in,
                              void* d_out, int out_size) {
    const float* x_re = (const float*)d_in[0];
    const float* x_im = (const float*)d_in[1];
    const float* rw   = (const float*)d_in[2];
    const float* cw   = (const float*)d_in[3];
    const float* swr  = (const float*)d_in[4];
    const float* swi  = (const float*)d_in[5];
    const float* sbr  = (const float*)d_in[6];
    const float* sbi  = (const float*)d_in[7];
    float* out = (float*)d_out;

    cudaFuncSetAttribute(gemm_kernel, cudaFuncAttributeMaxDynamicSharedMemorySize, SMEM_TOTAL);

    bias_kernel<<<2, 256>>>(sbr, sbi);
    pack_kernel<<<(N_TOT * K_TOT) / 256, 256>>>(rw, cw, swr, swi);
    basis_kernel<<<B_DIM, I_DIM>>>(x_re, x_im);

    dim3 grid(B_DIM / BM, N_TOT / BN);   // 64 x 4 = 256 CTAs
    gemm_kernel<<<grid, 256, SMEM_TOTAL>>>(out);
}

// round 10
// speedup vs baseline: 1.0280x; 1.0280x over previous
#include <cuda_runtime.h>
#include <cuda_fp16.h>
#include <cstdint>
#include <cstddef>

#define B_DIM   4096
#define I_DIM   256
#define O_DIM   256
#define K_BASIS (I_DIM * 64)                /* 16384 */
#define K_TOT   (K_BASIS + 2 * I_DIM)       /* 16896 */
#define N_TOT   (2 * O_DIM)                 /* 512   */

#define BM 128
#define BN 128
#define BK 64                                /* 128 bytes per k-row */
#define STAGES 4
#define NITER (K_TOT / BK)                   /* 264 */

#define STAGE_BYTES ((BM + BN) * 128)        /* 32 KB */
#define SMEM_TOTAL  (STAGES * STAGE_BYTES)   /* 128 KB */

// ---------------- device scratch ----------------
__device__ __align__(128) __half g_A[(size_t)B_DIM * K_TOT];   // 138 MB fp16 A
__device__ __align__(128) __half g_Wt[(size_t)N_TOT * K_TOT];  // 17 MB packed W^T [n][k]
__device__ float g_bias[N_TOT];

// ---------------- PTX helpers ----------------
__device__ __forceinline__ uint32_t smem_u32(const void* p) {
    uint32_t a;
    asm("{ .reg .u64 t; cvta.to.shared.u64 t, %1; cvt.u32.u64 %0, t; }" : "=r"(a) : "l"(p));
    return a;
}
__device__ __forceinline__ void cp_async16(uint32_t saddr, const void* gptr) {
    asm volatile("cp.async.cg.shared.global [%0], [%1], 16;\n" :: "r"(saddr), "l"(gptr));
}
#define CP_COMMIT() asm volatile("cp.async.commit_group;\n" ::: "memory")
#define CP_WAIT(N)  asm volatile("cp.async.wait_group %0;\n" :: "n"(N) : "memory")

__device__ __forceinline__ void ldsm_x4(uint32_t* r, uint32_t saddr) {
    asm volatile("ldmatrix.sync.aligned.m8n8.x4.shared.b16 {%0,%1,%2,%3}, [%4];"
                 : "=r"(r[0]), "=r"(r[1]), "=r"(r[2]), "=r"(r[3]) : "r"(saddr));
}
__device__ __forceinline__ void mma16816(float* d, const uint32_t* a, const uint32_t* b) {
    asm volatile(
        "mma.sync.aligned.m16n8k16.row.col.f32.f16.f16.f32 "
        "{%0,%1,%2,%3}, {%4,%5,%6,%7}, {%8,%9}, {%0,%1,%2,%3};\n"
        : "+f"(d[0]), "+f"(d[1]), "+f"(d[2]), "+f"(d[3])
        : "r"(a[0]), "r"(a[1]), "r"(a[2]), "r"(a[3]), "r"(b[0]), "r"(b[1]));
}

// ---------------- kernel 1: bias vector ----------------
__global__ void bias_kernel(const float* __restrict__ br, const float* __restrict__ bi) {
    int n = blockIdx.x * blockDim.x + threadIdx.x;
    if (n >= N_TOT) return;
    const float* src = (n < O_DIM) ? br : bi;
    int o = n & (O_DIM - 1);
    float s = 0.f;
    for (int i = 0; i < I_DIM; ++i) s += src[i * O_DIM + o];
    g_bias[n] = s;
}

// ---------------- kernel 2: pack W^T [n][k] fp16 ----------------
__global__ void pack_kernel(const float* __restrict__ rw, const float* __restrict__ cw,
                            const float* __restrict__ swr, const float* __restrict__ swi) {
    int gid = blockIdx.x * blockDim.x + threadIdx.x;
    int n = gid / K_TOT;
    int k = gid - n * K_TOT;
    int o = n & (O_DIM - 1);
    bool re = (n < O_DIM);
    float val;
    if (k < K_BASIS) {
        int i = k >> 6, uv = k & 63;
        const float* w = re ? rw : cw;
        val = w[((size_t)(i * O_DIM + o)) * 64 + uv];
    } else if (k < K_BASIS + I_DIM) {
        int i = k - K_BASIS;
        val = re ? swr[i * O_DIM + o] : swi[i * O_DIM + o];
    } else {
        int i = k - K_BASIS - I_DIM;
        val = re ? -swi[i * O_DIM + o] : swr[i * O_DIM + o];
    }
    g_Wt[(size_t)n * K_TOT + k] = __float2half(val);
}

// ---------------- kernel 3: materialize A (vectorized stores) ----------------
__global__ void basis_kernel(const float* __restrict__ x_re, const float* __restrict__ x_im) {
    int b = blockIdx.x;
    int i = threadIdx.x;
    float xr = x_re[b * I_DIM + i];
    float xi = x_im[b * I_DIM + i];
    float eu[8], ev[8];
#pragma unroll
    for (int u = 0; u < 8; ++u) {
        float lu = -2.0f + (float)u * (4.0f / 7.0f);
        float dr = xr - lu;  eu[u] = __expf(-dr * dr);
        float di = xi - lu;  ev[u] = __expf(-di * di);
    }
    uint4* dst = (uint4*)(g_A + (size_t)b * K_TOT + (size_t)i * 64);
#pragma unroll
    for (int u = 0; u < 8; ++u) {
        uint4 row;
        __half2* h = (__half2*)&row;
#pragma unroll
        for (int v = 0; v < 8; v += 2)
            h[v >> 1] = __floats2half2_rn(eu[u] * ev[v], eu[u] * ev[v + 1]);
        dst[u] = row;
    }
    float sr = xr / (1.f + __expf(-xr));
    float si = xi / (1.f + __expf(-xi));
    g_A[(size_t)b * K_TOT + K_BASIS + i]         = __float2half(sr);
    g_A[(size_t)b * K_TOT + K_BASIS + I_DIM + i] = __float2half(si);
}

// ---------------- kernel 4: GEMM (ldmatrix double-buffered + mma.sync) ----------------
// stage layout: A tile [128 rows][128B], then B tile [128 rows][128B]
// swizzle: 16B chunk c of row r stored at (c ^ (r & 7))
__device__ __forceinline__ void copy_stage(uint32_t sA, uint32_t sB,
                                           const __half* gA, const __half* gB,
                                           int k0, int tid) {
#pragma unroll
    for (int r = 0; r < 4; ++r) {
        int cc  = tid + (r << 8);          // 0..1023 16B-chunk index per operand
        int row = cc >> 3, ch = cc & 7;
        uint32_t d = (uint32_t)(row << 7) + (uint32_t)((ch ^ (row & 7)) << 4);
        cp_async16(sA + d, gA + (size_t)row * K_TOT + k0 + (ch << 3));
        cp_async16(sB + d, gB + (size_t)row * K_TOT + k0 + (ch << 3));
    }
}

__global__ __launch_bounds__(256, 1)
void gemm_kernel(float* __restrict__ out) {
    extern __shared__ __align__(128) char smem[];
    uint32_t sbase = smem_u32(smem);

    int tid  = threadIdx.x;
    int warp = tid >> 5, lane = tid & 31;
    int bm = blockIdx.x * BM, bn = blockIdx.y * BN;
    int wm = (warp >> 2) * 64;   // warp M offset (0,64)
    int wn = (warp & 3) * 32;    // warp N offset (0..96)

    // ldmatrix per-lane addressing constants
    int ra  = wm + (((lane >> 3) & 1) << 3) + (lane & 7);  // A row (without mi*16)
    int ca  = lane >> 4;                                   // A k16-half chunk select
    int swa = ra & 7;
    int nb  = wn + ((lane >> 4) << 3) + (lane & 7);        // B row (without nn*16)
    int cb  = (lane >> 3) & 1;                             // B k16-half chunk select
    int swb = nb & 7;

    const __half* gA = g_A  + (size_t)bm * K_TOT;
    const __half* gB = g_Wt + (size_t)bn * K_TOT;

    float acc[4][4][4];
#pragma unroll
    for (int mi = 0; mi < 4; ++mi)
#pragma unroll
        for (int ni = 0; ni < 4; ++ni)
#pragma unroll
            for (int c = 0; c < 4; ++c) acc[mi][ni][c] = 0.f;

    // prologue
#pragma unroll
    for (int t = 0; t < STAGES - 1; ++t) {
        copy_stage(sbase + t * STAGE_BYTES, sbase + t * STAGE_BYTES + BM * 128,
                   gA, gB, t * BK, tid);
        CP_COMMIT();
    }

    uint32_t af[2][4][4];
    uint32_t bf[2][4][2];

    int s = 0;
    for (int kt = 0; kt < NITER; ++kt) {
        CP_WAIT(STAGES - 2);
        __syncthreads();

        uint32_t baseA = sbase + s * STAGE_BYTES + (uint32_t)(ra << 7);
        uint32_t baseB = sbase + s * STAGE_BYTES + BM * 128 + (uint32_t)(nb << 7);

        // issue ks=0 fragment loads FIRST so their latency overlaps the
        // cp.async issue burst below
        {
            uint32_t offA = (uint32_t)((ca ^ swa) << 4);
            uint32_t offB = (uint32_t)((cb ^ swb) << 4);
#pragma unroll
            for (int mi = 0; mi < 4; ++mi)
                ldsm_x4(af[0][mi], baseA + (uint32_t)(mi * 16 * 128) + offA);
#pragma unroll
            for (int nn = 0; nn < 2; ++nn) {
                uint32_t t4[4];
                ldsm_x4(t4, baseB + (uint32_t)(nn * 16 * 128) + offB);
                bf[0][2 * nn][0]     = t4[0];
                bf[0][2 * nn][1]     = t4[1];
                bf[0][2 * nn + 1][0] = t4[2];
                bf[0][2 * nn + 1][1] = t4[3];
            }
        }

        {   // next-stage global->shared copy, overlapped with MMA block below
            int knext = kt + STAGES - 1;
            if (knext < NITER) {
                int j = s - 1;
                if (j < 0) j += STAGES;                  // knext % STAGES
                copy_stage(sbase + j * STAGE_BYTES, sbase + j * STAGE_BYTES + BM * 128,
                           gA, gB, knext * BK, tid);
            }
            CP_COMMIT();
        }

#pragma unroll
        for (int ks = 0; ks < 4; ++ks) {               // four k16 steps per BK=64
            int cur = ks & 1, nxt = cur ^ 1;
            if (ks < 3) {                              // prefetch next k16 fragments
                uint32_t offA = (uint32_t)(((2 * (ks + 1) + ca) ^ swa) << 4);
                uint32_t offB = (uint32_t)(((2 * (ks + 1) + cb) ^ swb) << 4);
#pragma unroll
                for (int mi = 0; mi < 4; ++mi)
                    ldsm_x4(af[nxt][mi], baseA + (uint32_t)(mi * 16 * 128) + offA);
#pragma unroll
                for (int nn = 0; nn < 2; ++nn) {
                    uint32_t t4[4];
                    ldsm_x4(t4, baseB + (uint32_t)(nn * 16 * 128) + offB);
                    bf[nxt][2 * nn][0]     = t4[0];
                    bf[nxt][2 * nn][1]     = t4[1];
                    bf[nxt][2 * nn + 1][0] = t4[2];
                    bf[nxt][2 * nn + 1][1] = t4[3];
                }
            }
#pragma unroll
            for (int mi = 0; mi < 4; ++mi)
#pragma unroll
                for (int ni = 0; ni < 4; ++ni)
                    mma16816(acc[mi][ni], af[cur][mi], bf[cur][ni]);
        }
        if (++s == STAGES) s = 0;
    }

    // epilogue: out[(b*O + o)*2 + part] = acc + bias[n]
    int g = lane >> 2, t = lane & 3;
#pragma unroll
    for (int mi = 0; mi < 4; ++mi) {
#pragma unroll
        for (int ni = 0; ni < 4; ++ni) {
            int row0 = bm + wm + mi * 16 + g;
            int col0 = bn + wn + ni * 8 + 2 * t;
            float b0 = g_bias[col0];
            float b1 = g_bias[col0 + 1];
            int o0 = col0 & (O_DIM - 1);
            int part = col0 >> 8;          // whole 128-wide tile is same part
            size_t base0 = ((size_t)row0 * O_DIM + o0) * 2 + part;
            size_t base8 = ((size_t)(row0 + 8) * O_DIM + o0) * 2 + part;
            out[base0]     = acc[mi][ni][0] + b0;
            out[base0 + 2] = acc[mi][ni][1] + b1;
            out[base8]     = acc[mi][ni][2] + b0;
            out[base8 + 2] = acc[mi][ni][3] + b1;
        }
    }
}

// ---------------- launch ----------------
extern "C" void kernel_launch(void* const* d_in, const int* in_sizes, int n_in,
                              void* d_out, int out_size) {
    const float* x_re = (const float*)d_in[0];
    const float* x_im = (const float*)d_in[1];
    const float* rw   = (const float*)d_in[2];
    const float* cw   = (const float*)d_in[3];
    const float* swr  = (const float*)d_in[4];
    const float* swi  = (const float*)d_in[5];
    const float* sbr  = (const float*)d_in[6];
    const float* sbi  = (const float*)d_in[7];
    float* out = (float*)d_out;

    cudaFuncSetAttribute(gemm_kernel, cudaFuncAttributeMaxDynamicSharedMemorySize, SMEM_TOTAL);

    bias_kernel<<<2, 256>>>(sbr, sbi);
    pack_kernel<<<(N_TOT * K_TOT) / 256, 256>>>(rw, cw, swr, swi);
    basis_kernel<<<B_DIM, I_DIM>>>(x_re, x_im);

    dim3 grid(B_DIM / BM, N_TOT / BN);   // 32 x 4 = 128 CTAs
    gemm_kernel<<<grid, 256, SMEM_TOTAL>>>(out);
}

// round 11
// speedup vs baseline: 1.1273x; 1.0966x over previous
#include <cuda_runtime.h>
#include <cuda_fp16.h>
#include <cstdint>
#include <cstddef>

#define B_DIM   4096
#define I_DIM   256
#define O_DIM   256
#define K_BASIS (I_DIM * 64)                /* 16384 */
#define K_TOT   (K_BASIS + 2 * I_DIM)       /* 16896 */
#define N_TOT   (2 * O_DIM)                 /* 512   */

#define BM 128
#define BN 128
#define BK 64                                /* 128 bytes per k-row */
#define STAGES 4
#define NITER (K_TOT / BK)                   /* 264 */

#define STAGE_BYTES ((BM + BN) * 128)        /* 32 KB */
#define OFF_STAGE   1024
#define SMEM_TOTAL  (OFF_STAGE + STAGES * STAGE_BYTES)   /* ~129 KB */

// ---------------- device scratch ----------------
__device__ __align__(128) __half g_A[(size_t)B_DIM * K_TOT];   // 138 MB fp16 A
__device__ __align__(128) __half g_Wt[(size_t)N_TOT * K_TOT];  // 17 MB packed W^T [n][k]
__device__ float g_bias[N_TOT];

// ---------------- PTX helpers ----------------
__device__ __forceinline__ uint32_t smem_u32(const void* p) {
    uint32_t a;
    asm("{ .reg .u64 t; cvta.to.shared.u64 t, %1; cvt.u32.u64 %0, t; }" : "=r"(a) : "l"(p));
    return a;
}
__device__ __forceinline__ void cp_async16(uint32_t saddr, const void* gptr) {
    asm volatile("cp.async.cg.shared.global [%0], [%1], 16;\n" :: "r"(saddr), "l"(gptr));
}
#define CP_COMMIT() asm volatile("cp.async.commit_group;\n" ::: "memory")

#define MBAR_INIT(a, cnt) \
    asm volatile("mbarrier.init.shared.b64 [%0], %1;" :: "r"(a), "r"((uint32_t)(cnt)) : "memory")
#define MBAR_ARRIVE(a) \
    asm volatile("mbarrier.arrive.shared.b64 _, [%0];" :: "r"(a) : "memory")
// arrive fires when all prior cp.async of this thread have completed; counts against init
#define CPASYNC_MBAR_ARRIVE(a) \
    asm volatile("cp.async.mbarrier.arrive.noinc.shared.b64 [%0];" :: "r"(a) : "memory")

__device__ __forceinline__ void mbar_wait(uint32_t mbar, uint32_t parity) {
    asm volatile(
        "{\n\t.reg .pred P1;\n\t"
        "WL_%=:\n\t"
        "mbarrier.try_wait.parity.acquire.cta.shared::cta.b64 P1, [%0], %1, 0x989680;\n\t"
        "@P1 bra.uni WD_%=;\n\t"
        "bra.uni WL_%=;\n\t"
        "WD_%=:\n\t}"
        :: "r"(mbar), "r"(parity) : "memory");
}

__device__ __forceinline__ void ldsm_x4(uint32_t* r, uint32_t saddr) {
    asm volatile("ldmatrix.sync.aligned.m8n8.x4.shared.b16 {%0,%1,%2,%3}, [%4];"
                 : "=r"(r[0]), "=r"(r[1]), "=r"(r[2]), "=r"(r[3]) : "r"(saddr));
}
__device__ __forceinline__ void mma16816(float* d, const uint32_t* a, const uint32_t* b) {
    asm volatile(
        "mma.sync.aligned.m16n8k16.row.col.f32.f16.f16.f32 "
        "{%0,%1,%2,%3}, {%4,%5,%6,%7}, {%8,%9}, {%0,%1,%2,%3};\n"
        : "+f"(d[0]), "+f"(d[1]), "+f"(d[2]), "+f"(d[3])
        : "r"(a[0]), "r"(a[1]), "r"(a[2]), "r"(a[3]), "r"(b[0]), "r"(b[1]));
}

// ---------------- kernel 1: bias vector ----------------
__global__ void bias_kernel(const float* __restrict__ br, const float* __restrict__ bi) {
    int n = blockIdx.x * blockDim.x + threadIdx.x;
    if (n >= N_TOT) return;
    const float* src = (n < O_DIM) ? br : bi;
    int o = n & (O_DIM - 1);
    float s = 0.f;
    for (int i = 0; i < I_DIM; ++i) s += src[i * O_DIM + o];
    g_bias[n] = s;
}

// ---------------- kernel 2: pack W^T [n][k] fp16 ----------------
__global__ void pack_kernel(const float* __restrict__ rw, const float* __restrict__ cw,
                            const float* __restrict__ swr, const float* __restrict__ swi) {
    int gid = blockIdx.x * blockDim.x + threadIdx.x;
    int n = gid / K_TOT;
    int k = gid - n * K_TOT;
    int o = n & (O_DIM - 1);
    bool re = (n < O_DIM);
    float val;
    if (k < K_BASIS) {
        int i = k >> 6, uv = k & 63;
        const float* w = re ? rw : cw;
        val = w[((size_t)(i * O_DIM + o)) * 64 + uv];
    } else if (k < K_BASIS + I_DIM) {
        int i = k - K_BASIS;
        val = re ? swr[i * O_DIM + o] : swi[i * O_DIM + o];
    } else {
        int i = k - K_BASIS - I_DIM;
        val = re ? -swi[i * O_DIM + o] : swr[i * O_DIM + o];
    }
    g_Wt[(size_t)n * K_TOT + k] = __float2half(val);
}

// ---------------- kernel 3: materialize A (vectorized stores) ----------------
__global__ void basis_kernel(const float* __restrict__ x_re, const float* __restrict__ x_im) {
    int b = blockIdx.x;
    int i = threadIdx.x;
    float xr = x_re[b * I_DIM + i];
    float xi = x_im[b * I_DIM + i];
    float eu[8], ev[8];
#pragma unroll
    for (int u = 0; u < 8; ++u) {
        float lu = -2.0f + (float)u * (4.0f / 7.0f);
        float dr = xr - lu;  eu[u] = __expf(-dr * dr);
        float di = xi - lu;  ev[u] = __expf(-di * di);
    }
    uint4* dst = (uint4*)(g_A + (size_t)b * K_TOT + (size_t)i * 64);
#pragma unroll
    for (int u = 0; u < 8; ++u) {
        uint4 row;
        __half2* h = (__half2*)&row;
#pragma unroll
        for (int v = 0; v < 8; v += 2)
            h[v >> 1] = __floats2half2_rn(eu[u] * ev[v], eu[u] * ev[v + 1]);
        dst[u] = row;
    }
    float sr = xr / (1.f + __expf(-xr));
    float si = xi / (1.f + __expf(-xi));
    g_A[(size_t)b * K_TOT + K_BASIS + i]         = __float2half(sr);
    g_A[(size_t)b * K_TOT + K_BASIS + I_DIM + i] = __float2half(si);
}

// ---------------- kernel 4: GEMM, warp-specialized ----------------
// warps 0-3: consumers, 64x64 warp tile. warps 4-7: producers (cp.async only).
// stage layout: A tile [128 rows][128B], then B tile [128 rows][128B]
// swizzle: 16B chunk c of row r stored at (c ^ (r & 7))
__global__ __launch_bounds__(256, 1)
void gemm_kernel(float* __restrict__ out) {
    extern __shared__ __align__(128) char smem[];
    uint32_t sb = smem_u32(smem);

    int tid  = threadIdx.x;
    int warp = tid >> 5, lane = tid & 31;
    int bm = blockIdx.x * BM, bn = blockIdx.y * BN;

    if (tid == 0) {
#pragma unroll
        for (int s = 0; s < STAGES; ++s) {
            MBAR_INIT(sb + s * 16, 128);      // full[s]: 128 producer threads
            MBAR_INIT(sb + s * 16 + 8, 128);  // empty[s]: 128 consumer threads
        }
    }
    __syncthreads();

    if (warp >= 4) {
        // ---------------- producer ----------------
        int ptid = tid - 128;                 // 0..127
        const __half* gA = g_A  + (size_t)bm * K_TOT;
        const __half* gB = g_Wt + (size_t)bn * K_TOT;
        int s = 0, phase = 1;                 // first empty-wait passes immediately
        for (int kt = 0; kt < NITER; ++kt) {
            mbar_wait(sb + s * 16 + 8, (uint32_t)phase);
            uint32_t sA = sb + OFF_STAGE + s * STAGE_BYTES;
            uint32_t sB = sA + BM * 128;
            int k0 = kt * BK;
#pragma unroll
            for (int j = 0; j < 8; ++j) {
                int cc  = ptid + (j << 7);    // 0..1023 chunk index
                int row = cc >> 3, ch = cc & 7;
                uint32_t d = (uint32_t)(row << 7) + (uint32_t)((ch ^ (row & 7)) << 4);
                cp_async16(sA + d, gA + (size_t)row * K_TOT + k0 + (ch << 3));
                cp_async16(sB + d, gB + (size_t)row * K_TOT + k0 + (ch << 3));
            }
            CP_COMMIT();
            CPASYNC_MBAR_ARRIVE(sb + s * 16);
            if (++s == STAGES) { s = 0; phase ^= 1; }
        }
        return;
    }

    // ---------------- consumer: 64x64 warp tile ----------------
    int wm = (warp & 1) * 64;
    int wn = (warp >> 1) * 64;

    int ra  = wm + (((lane >> 3) & 1) << 3) + (lane & 7);  // A row (without mi*16)
    int ca  = lane >> 4;
    int swa = ra & 7;
    int nb  = wn + ((lane >> 4) << 3) + (lane & 7);        // B row (without nn*16)
    int cb  = (lane >> 3) & 1;
    int swb = nb & 7;

    float acc[4][8][4];
#pragma unroll
    for (int mi = 0; mi < 4; ++mi)
#pragma unroll
        for (int ni = 0; ni < 8; ++ni)
#pragma unroll
            for (int c = 0; c < 4; ++c) acc[mi][ni][c] = 0.f;

    int s = 0, phase = 0;
    for (int kt = 0; kt < NITER; ++kt) {
        mbar_wait(sb + s * 16, (uint32_t)phase);

        uint32_t baseA = sb + OFF_STAGE + s * STAGE_BYTES + (uint32_t)(ra << 7);
        uint32_t baseB = sb + OFF_STAGE + s * STAGE_BYTES + BM * 128 + (uint32_t)(nb << 7);

#pragma unroll
        for (int ks = 0; ks < 4; ++ks) {
            uint32_t af[4][4];
            uint32_t bf[8][2];
            uint32_t offA = (uint32_t)(((2 * ks + ca) ^ swa) << 4);
            uint32_t offB = (uint32_t)(((2 * ks + cb) ^ swb) << 4);
#pragma unroll
            for (int mi = 0; mi < 4; ++mi)
                ldsm_x4(af[mi], baseA + (uint32_t)(mi * 16 * 128) + offA);
#pragma unroll
            for (int nn = 0; nn < 4; ++nn) {
                uint32_t t4[4];
                ldsm_x4(t4, baseB + (uint32_t)(nn * 16 * 128) + offB);
                bf[2 * nn][0]     = t4[0];
                bf[2 * nn][1]     = t4[1];
                bf[2 * nn + 1][0] = t4[2];
                bf[2 * nn + 1][1] = t4[3];
            }
#pragma unroll
            for (int mi = 0; mi < 4; ++mi)
#pragma unroll
                for (int ni = 0; ni < 8; ++ni)
                    mma16816(acc[mi][ni], af[mi], bf[ni]);
        }
        MBAR_ARRIVE(sb + s * 16 + 8);
        if (++s == STAGES) { s = 0; phase ^= 1; }
    }

    // epilogue: out[(b*O + o)*2 + part] = acc + bias[n]
    int g = lane >> 2, t = lane & 3;
#pragma unroll
    for (int mi = 0; mi < 4; ++mi) {
#pragma unroll
        for (int ni = 0; ni < 8; ++ni) {
            int row0 = bm + wm + mi * 16 + g;
            int col0 = bn + wn + ni * 8 + 2 * t;
            float b0 = g_bias[col0];
            float b1 = g_bias[col0 + 1];
            int o0 = col0 & (O_DIM - 1);
            int part = col0 >> 8;          // whole 128-wide tile is same part
            size_t base0 = ((size_t)row0 * O_DIM + o0) * 2 + part;
            size_t base8 = ((size_t)(row0 + 8) * O_DIM + o0) * 2 + part;
            out[base0]     = acc[mi][ni][0] + b0;
            out[base0 + 2] = acc[mi][ni][1] + b1;
            out[base8]     = acc[mi][ni][2] + b0;
            out[base8 + 2] = acc[mi][ni][3] + b1;
        }
    }
}

// ---------------- launch ----------------
extern "C" void kernel_launch(void* const* d_in, const int* in_sizes, int n_in,
                              void* d_out, int out_size) {
    const float* x_re = (const float*)d_in[0];
    const float* x_im = (const float*)d_in[1];
    const float* rw   = (const float*)d_in[2];
    const float* cw   = (const float*)d_in[3];
    const float* swr  = (const float*)d_in[4];
    const float* swi  = (const float*)d_in[5];
    const float* sbr  = (const float*)d_in[6];
    const float* sbi  = (const float*)d_in[7];
    float* out = (float*)d_out;

    cudaFuncSetAttribute(gemm_kernel, cudaFuncAttributeMaxDynamicSharedMemorySize, SMEM_TOTAL);

    bias_kernel<<<2, 256>>>(sbr, sbi);
    pack_kernel<<<(N_TOT * K_TOT) / 256, 256>>>(rw, cw, swr, swi);
    basis_kernel<<<B_DIM, I_DIM>>>(x_re, x_im);

    dim3 grid(B_DIM / BM, N_TOT / BN);   // 32 x 4 = 128 CTAs
    gemm_kernel<<<grid, 256, SMEM_TOTAL>>>(out);
}

// round 12
// speedup vs baseline: 1.2385x; 1.0987x over previous
#include <cuda_runtime.h>
#include <cuda_fp16.h>
#include <cstdint>
#include <cstddef>

#define B_DIM   4096
#define I_DIM   256
#define O_DIM   256
#define K_BASIS (I_DIM * 64)                /* 16384 */
#define K_TOT   (K_BASIS + 2 * I_DIM)       /* 16896 */
#define N_TOT   (2 * O_DIM)                 /* 512   */

#define BM 128
#define BN 128
#define BK 128                               /* 256 bytes per k-row */
#define STAGES 3
#define NITER (K_TOT / BK)                   /* 132 */

#define STAGE_BYTES ((BM + BN) * 256)        /* 64 KB */
#define OFF_STAGE   1024
#define SMEM_TOTAL  (OFF_STAGE + STAGES * STAGE_BYTES)   /* ~193 KB */

#define NTHREADS 384                         /* 8 consumer + 4 producer warps */

// ---------------- device scratch ----------------
__device__ __align__(128) __half g_A[(size_t)B_DIM * K_TOT];   // 138 MB fp16 A
__device__ __align__(128) __half g_Wt[(size_t)N_TOT * K_TOT];  // 17 MB packed W^T [n][k]
__device__ float g_bias[N_TOT];

// ---------------- PTX helpers ----------------
__device__ __forceinline__ uint32_t smem_u32(const void* p) {
    uint32_t a;
    asm("{ .reg .u64 t; cvta.to.shared.u64 t, %1; cvt.u32.u64 %0, t; }" : "=r"(a) : "l"(p));
    return a;
}
__device__ __forceinline__ void cp_async16(uint32_t saddr, const void* gptr) {
    asm volatile("cp.async.cg.shared.global [%0], [%1], 16;\n" :: "r"(saddr), "l"(gptr));
}
#define CP_COMMIT() asm volatile("cp.async.commit_group;\n" ::: "memory")

#define MBAR_INIT(a, cnt) \
    asm volatile("mbarrier.init.shared.b64 [%0], %1;" :: "r"(a), "r"((uint32_t)(cnt)) : "memory")
#define MBAR_ARRIVE(a) \
    asm volatile("mbarrier.arrive.shared.b64 _, [%0];" :: "r"(a) : "memory")
// arrive fires when all prior cp.async of this thread have completed
#define CPASYNC_MBAR_ARRIVE(a) \
    asm volatile("cp.async.mbarrier.arrive.noinc.shared.b64 [%0];" :: "r"(a) : "memory")

__device__ __forceinline__ void mbar_wait(uint32_t mbar, uint32_t parity) {
    asm volatile(
        "{\n\t.reg .pred P1;\n\t"
        "WL_%=:\n\t"
        "mbarrier.try_wait.parity.acquire.cta.shared::cta.b64 P1, [%0], %1, 0x989680;\n\t"
        "@P1 bra.uni WD_%=;\n\t"
        "bra.uni WL_%=;\n\t"
        "WD_%=:\n\t}"
        :: "r"(mbar), "r"(parity) : "memory");
}

__device__ __forceinline__ void ldsm_x4(uint32_t* r, uint32_t saddr) {
    asm volatile("ldmatrix.sync.aligned.m8n8.x4.shared.b16 {%0,%1,%2,%3}, [%4];"
                 : "=r"(r[0]), "=r"(r[1]), "=r"(r[2]), "=r"(r[3]) : "r"(saddr));
}
__device__ __forceinline__ void mma16816(float* d, const uint32_t* a, const uint32_t* b) {
    asm volatile(
        "mma.sync.aligned.m16n8k16.row.col.f32.f16.f16.f32 "
        "{%0,%1,%2,%3}, {%4,%5,%6,%7}, {%8,%9}, {%0,%1,%2,%3};\n"
        : "+f"(d[0]), "+f"(d[1]), "+f"(d[2]), "+f"(d[3])
        : "r"(a[0]), "r"(a[1]), "r"(a[2]), "r"(a[3]), "r"(b[0]), "r"(b[1]));
}

// ---------------- kernel 1: bias vector ----------------
__global__ void bias_kernel(const float* __restrict__ br, const float* __restrict__ bi) {
    int n = blockIdx.x * blockDim.x + threadIdx.x;
    if (n >= N_TOT) return;
    const float* src = (n < O_DIM) ? br : bi;
    int o = n & (O_DIM - 1);
    float s = 0.f;
    for (int i = 0; i < I_DIM; ++i) s += src[i * O_DIM + o];
    g_bias[n] = s;
}

// ---------------- kernel 2: pack W^T [n][k] fp16 ----------------
__global__ void pack_kernel(const float* __restrict__ rw, const float* __restrict__ cw,
                            const float* __restrict__ swr, const float* __restrict__ swi) {
    int gid = blockIdx.x * blockDim.x + threadIdx.x;
    int n = gid / K_TOT;
    int k = gid - n * K_TOT;
    int o = n & (O_DIM - 1);
    bool re = (n < O_DIM);
    float val;
    if (k < K_BASIS) {
        int i = k >> 6, uv = k & 63;
        const float* w = re ? rw : cw;
        val = w[((size_t)(i * O_DIM + o)) * 64 + uv];
    } else if (k < K_BASIS + I_DIM) {
        int i = k - K_BASIS;
        val = re ? swr[i * O_DIM + o] : swi[i * O_DIM + o];
    } else {
        int i = k - K_BASIS - I_DIM;
        val = re ? -swi[i * O_DIM + o] : swr[i * O_DIM + o];
    }
    g_Wt[(size_t)n * K_TOT + k] = __float2half(val);
}

// ---------------- kernel 3: materialize A (vectorized stores) ----------------
__global__ void basis_kernel(const float* __restrict__ x_re, const float* __restrict__ x_im) {
    int b = blockIdx.x;
    int i = threadIdx.x;
    float xr = x_re[b * I_DIM + i];
    float xi = x_im[b * I_DIM + i];
    float eu[8], ev[8];
#pragma unroll
    for (int u = 0; u < 8; ++u) {
        float lu = -2.0f + (float)u * (4.0f / 7.0f);
        float dr = xr - lu;  eu[u] = __expf(-dr * dr);
        float di = xi - lu;  ev[u] = __expf(-di * di);
    }
    uint4* dst = (uint4*)(g_A + (size_t)b * K_TOT + (size_t)i * 64);
#pragma unroll
    for (int u = 0; u < 8; ++u) {
        uint4 row;
        __half2* h = (__half2*)&row;
#pragma unroll
        for (int v = 0; v < 8; v += 2)
            h[v >> 1] = __floats2half2_rn(eu[u] * ev[v], eu[u] * ev[v + 1]);
        dst[u] = row;
    }
    float sr = xr / (1.f + __expf(-xr));
    float si = xi / (1.f + __expf(-xi));
    g_A[(size_t)b * K_TOT + K_BASIS + i]         = __float2half(sr);
    g_A[(size_t)b * K_TOT + K_BASIS + I_DIM + i] = __float2half(si);
}

// ---------------- kernel 4: GEMM, warp-specialized, 2 consumers/SMSP ----------------
// warps 0-7: consumers, 64x32 warp tile (2m x 4n). warps 8-11: producers.
// k-row is 256B; swizzle within each 128B half: chunk ch of row r at
// ((ch & 7) ^ (r & 7)) * 16 + (ch >> 3) * 128
__global__ __launch_bounds__(NTHREADS, 1)
void gemm_kernel(float* __restrict__ out) {
    extern __shared__ __align__(128) char smem[];
    uint32_t sb = smem_u32(smem);

    int tid  = threadIdx.x;
    int warp = tid >> 5, lane = tid & 31;
    int bm = blockIdx.x * BM, bn = blockIdx.y * BN;

    if (tid == 0) {
#pragma unroll
        for (int s = 0; s < STAGES; ++s) {
            MBAR_INIT(sb + s * 16, 128);      // full[s]: 128 producer threads
            MBAR_INIT(sb + s * 16 + 8, 256);  // empty[s]: 256 consumer threads
        }
    }
    __syncthreads();

    if (warp >= 8) {
        // ---------------- producer ----------------
        int ptid = tid - 256;                 // 0..127
        const __half* gA = g_A  + (size_t)bm * K_TOT;
        const __half* gB = g_Wt + (size_t)bn * K_TOT;
        int s = 0, phase = 1;                 // first empty-wait passes immediately
        for (int kt = 0; kt < NITER; ++kt) {
            mbar_wait(sb + s * 16 + 8, (uint32_t)phase);
            uint32_t sA = sb + OFF_STAGE + s * STAGE_BYTES;
            uint32_t sB = sA + BM * 256;
            int k0 = kt * BK;
#pragma unroll
            for (int j = 0; j < 16; ++j) {    // A: 2048 chunks, B: 2048 chunks
                int cc  = ptid + (j << 7);
                int row = cc >> 4, ch = cc & 15;
                uint32_t d = (uint32_t)(row << 8)
                           + (uint32_t)(((ch & 7) ^ (row & 7)) << 4)
                           + (uint32_t)((ch >> 3) << 7);
                cp_async16(sA + d, gA + (size_t)row * K_TOT + k0 + (ch << 3));
                cp_async16(sB + d, gB + (size_t)row * K_TOT + k0 + (ch << 3));
            }
            CP_COMMIT();
            CPASYNC_MBAR_ARRIVE(sb + s * 16);
            if (++s == STAGES) { s = 0; phase ^= 1; }
        }
        return;
    }

    // ---------------- consumer: 64x32 warp tile ----------------
    int wm = (warp & 1) * 64;                 // 2 m-warps
    int wn = (warp >> 1) * 32;                // 4 n-warps

    int ra  = wm + (((lane >> 3) & 1) << 3) + (lane & 7);  // A row (without mi*16)
    int ca  = lane >> 4;                                   // 0/1: k16 half
    int swa = ra & 7;
    int nb  = wn + ((lane >> 4) << 3) + (lane & 7);        // B row (without nn*16)
    int cb  = (lane >> 3) & 1;
    int swb = nb & 7;

    float acc[4][4][4];
#pragma unroll
    for (int mi = 0; mi < 4; ++mi)
#pragma unroll
        for (int ni = 0; ni < 4; ++ni)
#pragma unroll
            for (int c = 0; c < 4; ++c) acc[mi][ni][c] = 0.f;

    int s = 0, phase = 0;
    for (int kt = 0; kt < NITER; ++kt) {
        mbar_wait(sb + s * 16, (uint32_t)phase);

        uint32_t baseA = sb + OFF_STAGE + s * STAGE_BYTES + (uint32_t)(ra << 8);
        uint32_t baseB = sb + OFF_STAGE + s * STAGE_BYTES + BM * 256 + (uint32_t)(nb << 8);

#pragma unroll
        for (int ks = 0; ks < 8; ++ks) {       // eight k16 steps per BK=128
            uint32_t af[4][4];
            uint32_t bf[4][2];
            int chA = 2 * ks + ca;
            int chB = 2 * ks + cb;
            uint32_t offA = (uint32_t)((((chA & 7) ^ swa) << 4) + ((chA >> 3) << 7));
            uint32_t offB = (uint32_t)((((chB & 7) ^ swb) << 4) + ((chB >> 3) << 7));
#pragma unroll
            for (int mi = 0; mi < 4; ++mi)
                ldsm_x4(af[mi], baseA + (uint32_t)(mi * 16 * 256) + offA);
#pragma unroll
            for (int nn = 0; nn < 2; ++nn) {
                uint32_t t4[4];
                ldsm_x4(t4, baseB + (uint32_t)(nn * 16 * 256) + offB);
                bf[2 * nn][0]     = t4[0];
                bf[2 * nn][1]     = t4[1];
                bf[2 * nn + 1][0] = t4[2];
                bf[2 * nn + 1][1] = t4[3];
            }
#pragma unroll
            for (int mi = 0; mi < 4; ++mi)
#pragma unroll
                for (int ni = 0; ni < 4; ++ni)
                    mma16816(acc[mi][ni], af[mi], bf[ni]);
        }
        MBAR_ARRIVE(sb + s * 16 + 8);
        if (++s == STAGES) { s = 0; phase ^= 1; }
    }

    // epilogue: out[(b*O + o)*2 + part] = acc + bias[n]
    int g = lane >> 2, t = lane & 3;
#pragma unroll
    for (int mi = 0; mi < 4; ++mi) {
#pragma unroll
        for (int ni = 0; ni < 4; ++ni) {
            int row0 = bm + wm + mi * 16 + g;
            int col0 = bn + wn + ni * 8 + 2 * t;
            float b0 = g_bias[col0];
            float b1 = g_bias[col0 + 1];
            int o0 = col0 & (O_DIM - 1);
            int part = col0 >> 8;          // whole 128-wide tile is same part
            size_t base0 = ((size_t)row0 * O_DIM + o0) * 2 + part;
            size_t base8 = ((size_t)(row0 + 8) * O_DIM + o0) * 2 + part;
            out[base0]     = acc[mi][ni][0] + b0;
            out[base0 + 2] = acc[mi][ni][1] + b1;
            out[base8]     = acc[mi][ni][2] + b0;
            out[base8 + 2] = acc[mi][ni][3] + b1;
        }
    }
}

// ---------------- launch ----------------
extern "C" void kernel_launch(void* const* d_in, const int* in_sizes, int n_in,
                              void* d_out, int out_size) {
    const float* x_re = (const float*)d_in[0];
    const float* x_im = (const float*)d_in[1];
    const float* rw   = (const float*)d_in[2];
    const float* cw   = (const float*)d_in[3];
    const float* swr  = (const float*)d_in[4];
    const float* swi  = (const float*)d_in[5];
    const float* sbr  = (const float*)d_in[6];
    const float* sbi  = (const float*)d_in[7];
    float* out = (float*)d_out;

    cudaFuncSetAttribute(gemm_kernel, cudaFuncAttributeMaxDynamicSharedMemorySize, SMEM_TOTAL);

    bias_kernel<<<2, 256>>>(sbr, sbi);
    pack_kernel<<<(N_TOT * K_TOT) / 256, 256>>>(rw, cw, swr, swi);
    basis_kernel<<<B_DIM, I_DIM>>>(x_re, x_im);

    dim3 grid(B_DIM / BM, N_TOT / BN);   // 32 x 4 = 128 CTAs
    gemm_kernel<<<grid, NTHREADS, SMEM_TOTAL>>>(out);
}